// round 4
// baseline (speedup 1.0000x reference)
#include <cuda_runtime.h>
#include <math.h>

// ---------------- problem constants ----------------
#define NMAX   20000
#define EMAX   400000
#define RREL   8
#define HDIM   256
#define ODIM   128
#define PITCH0 (9*HDIM)   // 2304: 8 relation blocks + root block (hidden layers)

// ---------------- static scratch (no cudaMalloc allowed) ----------------
__device__ __align__(16) float g_hr[(size_t)NMAX * PITCH0];   // 184 MB: [N, 9*do] packed hr+root
__device__ __align__(16) float g_h1[(size_t)NMAX * HDIM];
__device__ __align__(16) float g_h2[(size_t)NMAX * HDIM];
__device__ __align__(16) float g_relagg[(size_t)NMAX * HDIM];
__device__ __align__(16) float g_wcat[256 * PITCH0];          // packed [K, 9*do] weights
__device__ float g_projrel[RREL * HDIM];
__device__ float g_sc[NMAX * 9];                              // s_src[n,r] (r<8), s_dst[n] (slot 8)
__device__ float g_score[EMAX];
__device__ int   g_deg[NMAX];
__device__ int   g_rowptr[NMAX + 1];
__device__ int   g_cursor[NMAX];
__device__ int   g_eidx[EMAX];
__device__ int   g_cnt[NMAX * RREL];

// ---------------- prep kernels ----------------
__global__ void k_zero() {
    int i = blockIdx.x * blockDim.x + threadIdx.x;
    if (i < NMAX) g_deg[i] = 0;
    if (i < NMAX * RREL) g_cnt[i] = 0;
}

__global__ void k_degcnt(const int* __restrict__ dst, const int* __restrict__ et, int E) {
    int e = blockIdx.x * blockDim.x + threadIdx.x;
    if (e < E) {
        int d = dst[e];
        atomicAdd(&g_deg[d], 1);
        atomicAdd(&g_cnt[d * RREL + et[e]], 1);
    }
}

// exclusive scan of g_deg -> g_rowptr (and g_cursor copy). Single block, 1024 threads.
__global__ void k_scan(int n) {
    __shared__ int part[1024];
    int t = threadIdx.x;
    int per = (n + 1023) >> 10;
    int base = t * per;
    int s = 0;
    for (int i = 0; i < per; i++) { int idx = base + i; if (idx < n) s += g_deg[idx]; }
    part[t] = s; __syncthreads();
    for (int off = 1; off < 1024; off <<= 1) {
        int v = (t >= off) ? part[t - off] : 0;
        __syncthreads();
        part[t] += v;
        __syncthreads();
    }
    int run = (t > 0) ? part[t - 1] : 0;
    for (int i = 0; i < per; i++) {
        int idx = base + i;
        if (idx < n) { g_rowptr[idx] = run; g_cursor[idx] = run; run += g_deg[idx]; }
    }
    if (t == 1023) g_rowptr[n] = part[1023];
}

__global__ void k_fill(const int* __restrict__ dst, int E) {
    int e = blockIdx.x * blockDim.x + threadIdx.x;
    if (e < E) {
        int p = atomicAdd(&g_cursor[dst[e]], 1);
        g_eidx[p] = e;
    }
}

// proj_rel[r,c] = (rel_emb @ rel_proj_w)[r,c] + b[c]   (8 x 256, tiny)
__global__ void k_projrel(const float* __restrict__ re, const float* __restrict__ w,
                          const float* __restrict__ b) {
    int r = blockIdx.x, c = threadIdx.x;
    float s = b[c];
    for (int k = 0; k < HDIM; k++) s += re[r * HDIM + k] * w[k * HDIM + c];
    g_projrel[r * HDIM + c] = s;
}

// rel_agg[n,c] = sum_r cnt[n,r] * proj_rel[r,c]
__global__ void k_relagg() {
    int node = blockIdx.x, c = threadIdx.x;
    __shared__ float cc[RREL];
    if (c < RREL) cc[c] = (float)g_cnt[node * RREL + c];
    __syncthreads();
    float s = 0.f;
#pragma unroll
    for (int r = 0; r < RREL; r++) s += cc[r] * g_projrel[r * HDIM + c];
    g_relagg[(size_t)node * HDIM + c] = s;
}

// pack W_rel[r][k][c] (j<8) and W_root[k][c] (j==8) into g_wcat[k, j*do + c]
__global__ void k_repack(const float* __restrict__ Wr, const float* __restrict__ Wo,
                         int K, int dob) {
    int pitch = 9 * dob;
    int total = K * pitch;
    int i = blockIdx.x * blockDim.x + threadIdx.x;
    if (i >= total) return;
    int k = i / pitch;
    int rem = i - k * pitch;
    int j = rem / dob;
    int c = rem - j * dob;
    float v = (j < RREL) ? Wr[(size_t)j * K * dob + (size_t)k * dob + c]
                         : Wo[(size_t)k * dob + c];
    g_wcat[i] = v;
}

// ---------------- SGEMM: C[M,Nc] = A[M,256] * g_wcat[256,Nc] ----------------
// 128x128 block tile, BK=8, 256 threads, 8x8 per-thread microtile.
__global__ __launch_bounds__(256, 2)
void k_sgemm(const float* __restrict__ A, float* __restrict__ C, int M, int Nc) {
    const int K = 256;
    __shared__ float As[8][128];
    __shared__ float Bs[8][128];
    int tid = threadIdx.x;
    int tx = tid & 15, ty = tid >> 4;
    int bm = blockIdx.y * 128, bn = blockIdx.x * 128;

    float acc[8][8];
#pragma unroll
    for (int i = 0; i < 8; i++)
#pragma unroll
        for (int j = 0; j < 8; j++) acc[i][j] = 0.f;

    int arow = tid >> 1, acol = (tid & 1) * 4;
    int brow = tid >> 5, bcol = (tid & 31) * 4;
    bool aval = (bm + arow) < M;
    const float* Aptr = A + (size_t)(bm + arow) * K + acol;

    for (int k0 = 0; k0 < K; k0 += 8) {
        float4 av = aval ? *(const float4*)(Aptr + k0) : make_float4(0.f, 0.f, 0.f, 0.f);
        As[acol + 0][arow] = av.x;
        As[acol + 1][arow] = av.y;
        As[acol + 2][arow] = av.z;
        As[acol + 3][arow] = av.w;
        float4 bv = *(const float4*)(g_wcat + (size_t)(k0 + brow) * Nc + bn + bcol);
        *(float4*)(&Bs[brow][bcol]) = bv;
        __syncthreads();
#pragma unroll
        for (int k = 0; k < 8; k++) {
            float a[8], b[8];
            *(float4*)(a)     = *(const float4*)(&As[k][ty * 8]);
            *(float4*)(a + 4) = *(const float4*)(&As[k][ty * 8 + 4]);
            *(float4*)(b)     = *(const float4*)(&Bs[k][tx * 8]);
            *(float4*)(b + 4) = *(const float4*)(&Bs[k][tx * 8 + 4]);
#pragma unroll
            for (int i = 0; i < 8; i++)
#pragma unroll
                for (int j = 0; j < 8; j++) acc[i][j] += a[i] * b[j];
        }
        __syncthreads();
    }

#pragma unroll
    for (int i = 0; i < 8; i++) {
        int gr = bm + ty * 8 + i;
        if (gr < M) {
            float* cp = C + (size_t)gr * Nc + bn + tx * 8;
            *(float4*)cp       = make_float4(acc[i][0], acc[i][1], acc[i][2], acc[i][3]);
            *(float4*)(cp + 4) = make_float4(acc[i][4], acc[i][5], acc[i][6], acc[i][7]);
        }
    }
}

// s_src[n,r] = hr[n,r,:]·att_src ; s_dst slot (j==8) uses att_dst on root block
__global__ void k_sc(const float* __restrict__ hr, const float* __restrict__ asrc,
                     const float* __restrict__ adst, int n, int dob) {
    int pitch = 9 * dob;
    int gw = (blockIdx.x * blockDim.x + threadIdx.x) >> 5;
    int lane = threadIdx.x & 31;
    if (gw >= n * 9) return;
    int node = gw / 9, j = gw - node * 9;
    const float* row = hr + (size_t)node * pitch + j * dob;
    const float* att = (j < RREL) ? asrc : adst;
    float s = 0.f;
    for (int c = lane; c < dob; c += 32) s += row[c] * att[c];
#pragma unroll
    for (int o = 16; o; o >>= 1) s += __shfl_xor_sync(0xffffffffu, s, o);
    if (lane == 0) g_sc[gw] = s;
}

__global__ void k_score(const int* __restrict__ src, const int* __restrict__ dst,
                        const int* __restrict__ et, int E) {
    int e = blockIdx.x * blockDim.x + threadIdx.x;
    if (e >= E) return;
    float s = g_sc[src[e] * 9 + et[e]] + g_sc[dst[e] * 9 + 8];
    g_score[e] = (s > 0.f) ? s : 0.2f * s;   // leaky_relu(0.2)
}

// per-node softmax + weighted aggregation + layer epilogue.
// mode 0: h_out = h_in + relu(root + agg + rel_agg)   (hidden layers, dob=256)
// mode 1: h_out = root + agg                          (final layer, dob=128)
__global__ void k_agg(const float* __restrict__ hr, const int* __restrict__ src,
                      const int* __restrict__ et, const float* __restrict__ h_in,
                      float* __restrict__ h_out, int dob, int mode) {
    int node = blockIdx.x;
    int t = threadIdx.x;
    int bd = blockDim.x;
    int pitch = 9 * dob;
    int beg = g_rowptr[node];
    int deg = g_rowptr[node + 1] - beg;

    __shared__ float red[256];
    __shared__ float sw[128];
    __shared__ int   sb[128];

    float agg = 0.f;
    if (deg > 0) {
        // max over incoming scores
        float m = -1e30f;
        for (int i = t; i < deg; i += bd) m = fmaxf(m, g_score[g_eidx[beg + i]]);
        red[t] = m; __syncthreads();
        for (int o = bd >> 1; o; o >>= 1) {
            if (t < o) red[t] = fmaxf(red[t], red[t + o]);
            __syncthreads();
        }
        float mx = red[0];
        __syncthreads();

        float acc = 0.f, dpart = 0.f;
        for (int base = 0; base < deg; base += 128) {
            int cnt = min(128, deg - base);
            if (t < cnt) {
                int e = g_eidx[beg + base + t];
                float w = __expf(g_score[e] - mx);
                sw[t] = w;
                dpart += w;
                sb[t] = src[e] * pitch + et[e] * dob;
            }
            __syncthreads();
#pragma unroll 4
            for (int j = 0; j < cnt; j++) acc += sw[j] * hr[(size_t)sb[j] + t];
            __syncthreads();
        }
        red[t] = dpart; __syncthreads();
        for (int o = bd >> 1; o; o >>= 1) {
            if (t < o) red[t] += red[t + o];
            __syncthreads();
        }
        agg = acc / red[0];
    }

    float root = hr[(size_t)node * pitch + RREL * dob + t];
    if (mode == 1) {
        h_out[(size_t)node * dob + t] = root + agg;
    } else {
        float v = root + agg + g_relagg[(size_t)node * HDIM + t];
        h_out[(size_t)node * dob + t] = h_in[(size_t)node * dob + t] + fmaxf(v, 0.f);
    }
}

// ---------------- launcher ----------------
extern "C" void kernel_launch(void* const* d_in, const int* in_sizes, int n_in,
                              void* d_out, int out_size) {
    const float* x    = (const float*)d_in[0];
    const int*   ei   = (const int*)  d_in[1];
    const int*   et   = (const int*)  d_in[2];
    const float* remb = (const float*)d_in[3];
    const float* rpw  = (const float*)d_in[4];
    const float* rpb  = (const float*)d_in[5];
    const float* Wr[3] = {(const float*)d_in[6],  (const float*)d_in[10], (const float*)d_in[14]};
    const float* Wo[3] = {(const float*)d_in[7],  (const float*)d_in[11], (const float*)d_in[15]};
    const float* Av[3] = {(const float*)d_in[8],  (const float*)d_in[12], (const float*)d_in[16]};
    const float* Ad[3] = {(const float*)d_in[9],  (const float*)d_in[13], (const float*)d_in[17]};

    int N = in_sizes[0] / HDIM;     // 20000
    int E = in_sizes[2];            // 400000
    const int* srcp = ei;
    const int* dstp = ei + E;

    float *hr, *h1, *h2;
    cudaGetSymbolAddress((void**)&hr, g_hr);
    cudaGetSymbolAddress((void**)&h1, g_h1);
    cudaGetSymbolAddress((void**)&h2, g_h2);

    // ---- graph prep (layer-invariant) ----
    k_zero<<<(NMAX * RREL + 255) / 256, 256>>>();
    k_degcnt<<<(E + 255) / 256, 256>>>(dstp, et, E);
    k_scan<<<1, 1024>>>(N);
    k_fill<<<(E + 255) / 256, 256>>>(dstp, E);
    k_projrel<<<RREL, HDIM>>>(remb, rpw, rpb);
    k_relagg<<<N, HDIM>>>();

    // ---- three RGAT layers ----
    const float* hin = x;
    for (int l = 0; l < 3; l++) {
        int dob = (l == 2) ? ODIM : HDIM;
        int pitch = 9 * dob;

        int total = 256 * pitch;
        k_repack<<<(total + 255) / 256, 256>>>(Wr[l], Wo[l], 256, dob);

        dim3 g(pitch / 128, (N + 127) / 128);
        k_sgemm<<<g, 256>>>(hin, hr, N, pitch);

        int rows = N * 9;
        k_sc<<<(rows * 32 + 255) / 256, 256>>>(hr, Av[l], Ad[l], N, dob);
        k_score<<<(E + 255) / 256, 256>>>(srcp, dstp, et, E);

        float* hout = (l == 0) ? h1 : (l == 1) ? h2 : (float*)d_out;
        k_agg<<<N, dob>>>(hr, srcp, et, hin, hout, dob, (l == 2) ? 1 : 0);
        hin = hout;
    }
}

// round 6
// speedup vs baseline: 1.9238x; 1.9238x over previous
#include <cuda_runtime.h>
#include <cstdint>
#include <math.h>

// ---------------- problem constants ----------------
#define NMAX   20000
#define EMAX   400000
#define RREL   8
#define HDIM   256
#define ODIM   128
#define PITCH0 (9*HDIM)   // 2304

// GEMM tiling
#define BM 128
#define BN 128
#define KDIM 256
#define KC 32                 // K elems per smem chunk
#define NKC (KDIM/KC)         // 8 chunks
#define ASTRIDE 36            // padded smem row stride (floats): banks (4r+c)&31 distinct
#define CHUNK_FLOATS (128*ASTRIDE)
#define SMEM_BYTES (4*CHUNK_FLOATS*4)   // A0,A1,B0,B1 = 73728 B

// ---------------- static scratch ----------------
__device__ __align__(16) float g_hr[(size_t)NMAX * PITCH0];
__device__ __align__(16) float g_h1[(size_t)NMAX * HDIM];
__device__ __align__(16) float g_h2[(size_t)NMAX * HDIM];
__device__ __align__(16) float g_art[(size_t)NMAX * HDIM];    // tf32-rounded activations
__device__ __align__(16) float g_relagg[(size_t)NMAX * HDIM];
__device__ __align__(16) float g_wcat[(size_t)PITCH0 * KDIM]; // B K-major: [Nc][256], tf32-rounded
__device__ float g_projrel[RREL * HDIM];
__device__ float g_sc[NMAX * 9];
__device__ float g_score[EMAX];
__device__ int   g_deg[NMAX];
__device__ int   g_rowptr[NMAX + 1];
__device__ int   g_cursor[NMAX];
__device__ int   g_eidx[EMAX];
__device__ int   g_cnt[NMAX * RREL];

// ---------------- helpers ----------------
__device__ __forceinline__ uint32_t smem_u32(const void* p) {
    uint32_t a;
    asm("{ .reg .u64 t; cvta.to.shared.u64 t, %1; cvt.u32.u64 %0, t; }" : "=r"(a) : "l"(p));
    return a;
}
__device__ __forceinline__ float tf32_rn(float x) {
    uint32_t u;
    asm("cvt.rna.tf32.f32 %0, %1;" : "=r"(u) : "f"(x));
    return __uint_as_float(u);
}
__device__ __forceinline__ void cp_async16(uint32_t dst, const void* src, int src_sz) {
    asm volatile("cp.async.ca.shared.global [%0], [%1], 16, %2;"
                 :: "r"(dst), "l"(src), "r"(src_sz) : "memory");
}
__device__ __forceinline__ void mma_tf32(float& d0, float& d1, float& d2, float& d3,
                                         float a0, float a1, float a2, float a3,
                                         float b0, float b1) {
    asm volatile(
        "mma.sync.aligned.m16n8k8.row.col.f32.tf32.tf32.f32 "
        "{%0,%1,%2,%3}, {%4,%5,%6,%7}, {%8,%9}, {%0,%1,%2,%3};"
        : "+f"(d0), "+f"(d1), "+f"(d2), "+f"(d3)
        : "r"(__float_as_uint(a0)), "r"(__float_as_uint(a1)),
          "r"(__float_as_uint(a2)), "r"(__float_as_uint(a3)),
          "r"(__float_as_uint(b0)), "r"(__float_as_uint(b1)));
}

// ---------------- prep kernels ----------------
__global__ void k_zero() {
    int i = blockIdx.x * blockDim.x + threadIdx.x;
    if (i < NMAX) g_deg[i] = 0;
    if (i < NMAX * RREL) g_cnt[i] = 0;
}
__global__ void k_degcnt(const int* __restrict__ dst, const int* __restrict__ et, int E) {
    int e = blockIdx.x * blockDim.x + threadIdx.x;
    if (e < E) {
        int d = dst[e];
        atomicAdd(&g_deg[d], 1);
        atomicAdd(&g_cnt[d * RREL + et[e]], 1);
    }
}
__global__ void k_scan(int n) {
    __shared__ int part[1024];
    int t = threadIdx.x;
    int per = (n + 1023) >> 10;
    int base = t * per;
    int s = 0;
    for (int i = 0; i < per; i++) { int idx = base + i; if (idx < n) s += g_deg[idx]; }
    part[t] = s; __syncthreads();
    for (int off = 1; off < 1024; off <<= 1) {
        int v = (t >= off) ? part[t - off] : 0;
        __syncthreads(); part[t] += v; __syncthreads();
    }
    int run = (t > 0) ? part[t - 1] : 0;
    for (int i = 0; i < per; i++) {
        int idx = base + i;
        if (idx < n) { g_rowptr[idx] = run; g_cursor[idx] = run; run += g_deg[idx]; }
    }
    if (t == 1023) g_rowptr[n] = part[1023];
}
__global__ void k_fill(const int* __restrict__ dst, int E) {
    int e = blockIdx.x * blockDim.x + threadIdx.x;
    if (e < E) {
        int p = atomicAdd(&g_cursor[dst[e]], 1);
        g_eidx[p] = e;
    }
}
__global__ void k_projrel(const float* __restrict__ re, const float* __restrict__ w,
                          const float* __restrict__ b) {
    int r = blockIdx.x, c = threadIdx.x;
    float s = b[c];
    for (int k = 0; k < HDIM; k++) s += re[r * HDIM + k] * w[k * HDIM + c];
    g_projrel[r * HDIM + c] = s;
}
__global__ void k_relagg() {
    int node = blockIdx.x, c = threadIdx.x;
    __shared__ float cc[RREL];
    if (c < RREL) cc[c] = (float)g_cnt[node * RREL + c];
    __syncthreads();
    float s = 0.f;
#pragma unroll
    for (int r = 0; r < RREL; r++) s += cc[r] * g_projrel[r * HDIM + c];
    g_relagg[(size_t)node * HDIM + c] = s;
}

// transpose+round weights K-major: g_wcat[n*256 + k] = tf32(W[k][n]), n = j*dob + c
__global__ void k_repackT(const float* __restrict__ Wr, const float* __restrict__ Wo, int dob) {
    __shared__ float t[32][33];
    int j = blockIdx.z;
    int k0 = blockIdx.y * 32, c0 = blockIdx.x * 32;
    const float* W = (j < RREL) ? Wr + (size_t)j * KDIM * dob : Wo;
    for (int r = threadIdx.y; r < 32; r += 8)
        t[r][threadIdx.x] = W[(size_t)(k0 + r) * dob + c0 + threadIdx.x];
    __syncthreads();
    for (int r = threadIdx.y; r < 32; r += 8) {
        int n = j * dob + c0 + r;
        g_wcat[(size_t)n * KDIM + k0 + threadIdx.x] = tf32_rn(t[threadIdx.x][r]);
    }
}

// round activations to tf32 (removes HMMA truncation bias)
__global__ void k_round(const float* __restrict__ in, float* __restrict__ out, int n4) {
    int i = blockIdx.x * blockDim.x + threadIdx.x;
    if (i >= n4) return;
    float4 v = ((const float4*)in)[i];
    v.x = tf32_rn(v.x); v.y = tf32_rn(v.y); v.z = tf32_rn(v.z); v.w = tf32_rn(v.w);
    ((float4*)out)[i] = v;
}

// ---------------- tf32 mma.sync GEMM: C[M,Nc] = A[M,256] * g_wcat^T ----------------
// 128x128 CTA, 8 warps (4m x 2n), warp tile 32x64, K chunk 32, cp.async double buffer.
__global__ __launch_bounds__(256, 2)
void k_mma(const float* __restrict__ A, float* __restrict__ C, int M, int Nc) {
    extern __shared__ float sm[];
    float* sA[2] = { sm,                    sm + CHUNK_FLOATS };
    float* sB[2] = { sm + 2 * CHUNK_FLOATS, sm + 3 * CHUNK_FLOATS };

    int tid  = threadIdx.x;
    int wid  = tid >> 5, lane = tid & 31;
    int wm   = wid >> 1;           // 0..3 -> m offset
    int wn   = wid & 1;            // 0..1 -> n offset
    int bm   = blockIdx.y * BM, bn = blockIdx.x * BN;
    int lq   = lane >> 2;          // 0..7
    int lr   = lane & 3;           // 0..3

    float acc[2][8][4];
#pragma unroll
    for (int mt = 0; mt < 2; mt++)
#pragma unroll
        for (int nt = 0; nt < 8; nt++)
#pragma unroll
            for (int i = 0; i < 4; i++) acc[mt][nt][i] = 0.f;

    uint32_t sAb[2] = { smem_u32(sA[0]), smem_u32(sA[1]) };
    uint32_t sBb[2] = { smem_u32(sB[0]), smem_u32(sB[1]) };

    int lrow = tid >> 3;           // 0..31
    int lc4  = (tid & 7) * 4;      // 0..28

    auto load_chunk = [&](int buf, int kc) {
        int c0 = kc * KC;
#pragma unroll
        for (int it = 0; it < 4; it++) {
            int r = lrow + it * 32;
            uint32_t off = (uint32_t)(r * ASTRIDE + lc4) * 4u;
            const float* ga = A + (size_t)(bm + r) * KDIM + c0 + lc4;
            cp_async16(sAb[buf] + off, ga, (bm + r < M) ? 16 : 0);
            const float* gb = g_wcat + (size_t)(bn + r) * KDIM + c0 + lc4;
            cp_async16(sBb[buf] + off, gb, 16);
        }
        asm volatile("cp.async.commit_group;" ::: "memory");
    };

    load_chunk(0, 0);

    for (int kc = 0; kc < NKC; kc++) {
        int buf = kc & 1;
        if (kc + 1 < NKC) {
            load_chunk(buf ^ 1, kc + 1);
            asm volatile("cp.async.wait_group 1;" ::: "memory");
        } else {
            asm volatile("cp.async.wait_group 0;" ::: "memory");
        }
        __syncthreads();

        const float* a_s = sA[buf];
        const float* b_s = sB[buf];
#pragma unroll
        for (int k8 = 0; k8 < KC / 8; k8++) {
            int kb = k8 * 8 + lr;
            float afr[2][4];
#pragma unroll
            for (int mt = 0; mt < 2; mt++) {
                int r0 = wm * 32 + mt * 16 + lq;
                afr[mt][0] = a_s[r0 * ASTRIDE + kb];
                afr[mt][1] = a_s[(r0 + 8) * ASTRIDE + kb];
                afr[mt][2] = a_s[r0 * ASTRIDE + kb + 4];
                afr[mt][3] = a_s[(r0 + 8) * ASTRIDE + kb + 4];
            }
            float bfr[8][2];
#pragma unroll
            for (int nt = 0; nt < 8; nt++) {
                int n0 = wn * 64 + nt * 8 + lq;
                bfr[nt][0] = b_s[n0 * ASTRIDE + kb];
                bfr[nt][1] = b_s[n0 * ASTRIDE + kb + 4];
            }
#pragma unroll
            for (int mt = 0; mt < 2; mt++)
#pragma unroll
                for (int nt = 0; nt < 8; nt++)
                    mma_tf32(acc[mt][nt][0], acc[mt][nt][1], acc[mt][nt][2], acc[mt][nt][3],
                             afr[mt][0], afr[mt][1], afr[mt][2], afr[mt][3],
                             bfr[nt][0], bfr[nt][1]);
        }
        __syncthreads();
    }

    // epilogue: D rows per thread: r0 = base+lane/4, r1 = r0+8; cols 2*(lane%4), +1
#pragma unroll
    for (int mt = 0; mt < 2; mt++) {
        int r0 = bm + wm * 32 + mt * 16 + lq;
#pragma unroll
        for (int nt = 0; nt < 8; nt++) {
            int col = bn + wn * 64 + nt * 8 + 2 * lr;
            if (r0 < M)
                *(float2*)(C + (size_t)r0 * Nc + col) =
                    make_float2(acc[mt][nt][0], acc[mt][nt][1]);
            if (r0 + 8 < M)
                *(float2*)(C + (size_t)(r0 + 8) * Nc + col) =
                    make_float2(acc[mt][nt][2], acc[mt][nt][3]);
        }
    }
}

// ---------------- attention / aggregation ----------------
__global__ void k_sc(const float* __restrict__ hr, const float* __restrict__ asrc,
                     const float* __restrict__ adst, int n, int dob) {
    int pitch = 9 * dob;
    int gw = (blockIdx.x * blockDim.x + threadIdx.x) >> 5;
    int lane = threadIdx.x & 31;
    if (gw >= n * 9) return;
    int node = gw / 9, j = gw - node * 9;
    const float* row = hr + (size_t)node * pitch + j * dob;
    const float* att = (j < RREL) ? asrc : adst;
    float s = 0.f;
    for (int c = lane; c < dob; c += 32) s += row[c] * att[c];
#pragma unroll
    for (int o = 16; o; o >>= 1) s += __shfl_xor_sync(0xffffffffu, s, o);
    if (lane == 0) g_sc[gw] = s;
}

__global__ void k_score(const int* __restrict__ src, const int* __restrict__ dst,
                        const int* __restrict__ et, int E) {
    int e = blockIdx.x * blockDim.x + threadIdx.x;
    if (e >= E) return;
    float s = g_sc[src[e] * 9 + et[e]] + g_sc[dst[e] * 9 + 8];
    g_score[e] = (s > 0.f) ? s : 0.2f * s;
}

__global__ void k_agg(const float* __restrict__ hr, const int* __restrict__ src,
                      const int* __restrict__ et, const float* __restrict__ h_in,
                      float* __restrict__ h_out, int dob, int mode) {
    int node = blockIdx.x;
    int t = threadIdx.x;
    int bd = blockDim.x;
    int pitch = 9 * dob;
    int beg = g_rowptr[node];
    int deg = g_rowptr[node + 1] - beg;

    __shared__ float red[256];
    __shared__ float sw[128];
    __shared__ int   sb[128];

    float agg = 0.f;
    if (deg > 0) {
        float m = -1e30f;
        for (int i = t; i < deg; i += bd) m = fmaxf(m, g_score[g_eidx[beg + i]]);
        red[t] = m; __syncthreads();
        for (int o = bd >> 1; o; o >>= 1) {
            if (t < o) red[t] = fmaxf(red[t], red[t + o]);
            __syncthreads();
        }
        float mx = red[0];
        __syncthreads();

        float acc = 0.f, dpart = 0.f;
        for (int base = 0; base < deg; base += 128) {
            int cnt = min(128, deg - base);
            if (t < cnt) {
                int e = g_eidx[beg + base + t];
                float w = __expf(g_score[e] - mx);
                sw[t] = w;
                dpart += w;
                sb[t] = src[e] * pitch + et[e] * dob;
            }
            __syncthreads();
#pragma unroll 4
            for (int j = 0; j < cnt; j++) acc += sw[j] * hr[(size_t)sb[j] + t];
            __syncthreads();
        }
        red[t] = dpart; __syncthreads();
        for (int o = bd >> 1; o; o >>= 1) {
            if (t < o) red[t] += red[t + o];
            __syncthreads();
        }
        agg = acc / red[0];
    }

    float root = hr[(size_t)node * pitch + RREL * dob + t];
    if (mode == 1) {
        h_out[(size_t)node * dob + t] = root + agg;
    } else {
        float v = root + agg + g_relagg[(size_t)node * HDIM + t];
        h_out[(size_t)node * dob + t] = h_in[(size_t)node * dob + t] + fmaxf(v, 0.f);
    }
}

// ---------------- launcher ----------------
extern "C" void kernel_launch(void* const* d_in, const int* in_sizes, int n_in,
                              void* d_out, int out_size) {
    const float* x    = (const float*)d_in[0];
    const int*   ei   = (const int*)  d_in[1];
    const int*   et   = (const int*)  d_in[2];
    const float* remb = (const float*)d_in[3];
    const float* rpw  = (const float*)d_in[4];
    const float* rpb  = (const float*)d_in[5];
    const float* Wr[3] = {(const float*)d_in[6],  (const float*)d_in[10], (const float*)d_in[14]};
    const float* Wo[3] = {(const float*)d_in[7],  (const float*)d_in[11], (const float*)d_in[15]};
    const float* Av[3] = {(const float*)d_in[8],  (const float*)d_in[12], (const float*)d_in[16]};
    const float* Ad[3] = {(const float*)d_in[9],  (const float*)d_in[13], (const float*)d_in[17]};

    int N = in_sizes[0] / HDIM;     // 20000
    int E = in_sizes[2];            // 400000
    const int* srcp = ei;
    const int* dstp = ei + E;

    float *hr, *h1, *h2, *art;
    cudaGetSymbolAddress((void**)&hr,  g_hr);
    cudaGetSymbolAddress((void**)&h1,  g_h1);
    cudaGetSymbolAddress((void**)&h2,  g_h2);
    cudaGetSymbolAddress((void**)&art, g_art);

    cudaFuncSetAttribute(k_mma, cudaFuncAttributeMaxDynamicSharedMemorySize, SMEM_BYTES);

    // ---- graph prep (layer-invariant) ----
    k_zero<<<(NMAX * RREL + 255) / 256, 256>>>();
    k_degcnt<<<(E + 255) / 256, 256>>>(dstp, et, E);
    k_scan<<<1, 1024>>>(N);
    k_fill<<<(E + 255) / 256, 256>>>(dstp, E);
    k_projrel<<<RREL, HDIM>>>(remb, rpw, rpb);
    k_relagg<<<N, HDIM>>>();

    // ---- three RGAT layers ----
    const float* hin = x;
    for (int l = 0; l < 3; l++) {
        int dob = (l == 2) ? ODIM : HDIM;
        int pitch = 9 * dob;

        dim3 gt(dob / 32, KDIM / 32, 9);
        k_repackT<<<gt, dim3(32, 8)>>>(Wr[l], Wo[l], dob);

        int n4 = N * HDIM / 4;
        k_round<<<(n4 + 255) / 256, 256>>>(hin, art, n4);

        dim3 g(pitch / BN, (N + BM - 1) / BM);
        k_mma<<<g, 256, SMEM_BYTES>>>(art, hr, N, pitch);

        int rows = N * 9;
        k_sc<<<(rows * 32 + 255) / 256, 256>>>(hr, Av[l], Ad[l], N, dob);
        k_score<<<(E + 255) / 256, 256>>>(srcp, dstp, et, E);

        float* hout = (l == 0) ? h1 : (l == 1) ? h2 : (float*)d_out;
        k_agg<<<N, dob>>>(hr, srcp, et, hin, hout, dob, (l == 2) ? 1 : 0);
        hin = hout;
    }
}

// round 7
// speedup vs baseline: 2.4334x; 1.2649x over previous
#include <cuda_runtime.h>
#include <cstdint>
#include <math.h>

// ---------------- problem constants ----------------
#define NMAX   20000
#define EMAX   400000
#define RREL   8
#define HDIM   256
#define ODIM   128
#define PITCH0 (9*HDIM)   // 2304

// GEMM tiling
#define BM 128
#define BN 128
#define KDIM 256
#define KC 32
#define NKC (KDIM/KC)
#define ASTRIDE 36
#define CHUNK_FLOATS (128*ASTRIDE)
#define SMEM_BYTES (4*CHUNK_FLOATS*4)

// ---------------- static scratch ----------------
__device__ __align__(16) float g_hr[(size_t)NMAX * PITCH0];
__device__ __align__(16) float g_h1[(size_t)NMAX * HDIM];
__device__ __align__(16) float g_h2[(size_t)NMAX * HDIM];
__device__ __align__(16) float g_art[(size_t)NMAX * HDIM];    // tf32-rounded activations
__device__ __align__(16) float g_relagg[(size_t)NMAX * HDIM];
__device__ __align__(16) float g_wcat[(size_t)PITCH0 * KDIM]; // B K-major, tf32-rounded
__device__ float g_projrel[RREL * HDIM];
__device__ float g_sc[NMAX * 9];
__device__ float g_score[EMAX];
__device__ int   g_deg[NMAX];
__device__ int   g_rowptr[NMAX + 1];
__device__ int   g_cursor[NMAX];
__device__ int   g_eidx[EMAX];
__device__ int   g_cnt[NMAX * RREL];

// ---------------- helpers ----------------
__device__ __forceinline__ uint32_t smem_u32(const void* p) {
    uint32_t a;
    asm("{ .reg .u64 t; cvta.to.shared.u64 t, %1; cvt.u32.u64 %0, t; }" : "=r"(a) : "l"(p));
    return a;
}
__device__ __forceinline__ float tf32_rn(float x) {
    uint32_t u;
    asm("cvt.rna.tf32.f32 %0, %1;" : "=r"(u) : "f"(x));
    return __uint_as_float(u);
}
__device__ __forceinline__ void cp_async16(uint32_t dst, const void* src, int src_sz) {
    asm volatile("cp.async.ca.shared.global [%0], [%1], 16, %2;"
                 :: "r"(dst), "l"(src), "r"(src_sz) : "memory");
}
__device__ __forceinline__ void mma_tf32(float& d0, float& d1, float& d2, float& d3,
                                         float a0, float a1, float a2, float a3,
                                         float b0, float b1) {
    asm volatile(
        "mma.sync.aligned.m16n8k8.row.col.f32.tf32.tf32.f32 "
        "{%0,%1,%2,%3}, {%4,%5,%6,%7}, {%8,%9}, {%0,%1,%2,%3};"
        : "+f"(d0), "+f"(d1), "+f"(d2), "+f"(d3)
        : "r"(__float_as_uint(a0)), "r"(__float_as_uint(a1)),
          "r"(__float_as_uint(a2)), "r"(__float_as_uint(a3)),
          "r"(__float_as_uint(b0)), "r"(__float_as_uint(b1)));
}

// ---------------- prep kernels ----------------
__global__ void k_zero() {
    int i = blockIdx.x * blockDim.x + threadIdx.x;
    if (i < NMAX) g_deg[i] = 0;
    if (i < NMAX * RREL) g_cnt[i] = 0;
}
__global__ void k_zsc(int n9) {
    int i = blockIdx.x * blockDim.x + threadIdx.x;
    if (i < n9) g_sc[i] = 0.f;
}
__global__ void k_degcnt(const int* __restrict__ dst, const int* __restrict__ et, int E) {
    int e = blockIdx.x * blockDim.x + threadIdx.x;
    if (e < E) {
        int d = dst[e];
        atomicAdd(&g_deg[d], 1);
        atomicAdd(&g_cnt[d * RREL + et[e]], 1);
    }
}
__global__ void k_scan(int n) {
    __shared__ int part[1024];
    int t = threadIdx.x;
    int per = (n + 1023) >> 10;
    int base = t * per;
    int s = 0;
    for (int i = 0; i < per; i++) { int idx = base + i; if (idx < n) s += g_deg[idx]; }
    part[t] = s; __syncthreads();
    for (int off = 1; off < 1024; off <<= 1) {
        int v = (t >= off) ? part[t - off] : 0;
        __syncthreads(); part[t] += v; __syncthreads();
    }
    int run = (t > 0) ? part[t - 1] : 0;
    for (int i = 0; i < per; i++) {
        int idx = base + i;
        if (idx < n) { g_rowptr[idx] = run; g_cursor[idx] = run; run += g_deg[idx]; }
    }
    if (t == 1023) g_rowptr[n] = part[1023];
}
__global__ void k_fill(const int* __restrict__ dst, int E) {
    int e = blockIdx.x * blockDim.x + threadIdx.x;
    if (e < E) {
        int p = atomicAdd(&g_cursor[dst[e]], 1);
        g_eidx[p] = e;
    }
}
__global__ void k_projrel(const float* __restrict__ re, const float* __restrict__ w,
                          const float* __restrict__ b) {
    int r = blockIdx.x, c = threadIdx.x;
    float s = b[c];
    for (int k = 0; k < HDIM; k++) s += re[r * HDIM + k] * w[k * HDIM + c];
    g_projrel[r * HDIM + c] = s;
}
__global__ void k_relagg() {
    int node = blockIdx.x, c = threadIdx.x;
    __shared__ float cc[RREL];
    if (c < RREL) cc[c] = (float)g_cnt[node * RREL + c];
    __syncthreads();
    float s = 0.f;
#pragma unroll
    for (int r = 0; r < RREL; r++) s += cc[r] * g_projrel[r * HDIM + c];
    g_relagg[(size_t)node * HDIM + c] = s;
}
__global__ void k_repackT(const float* __restrict__ Wr, const float* __restrict__ Wo, int dob) {
    __shared__ float t[32][33];
    int j = blockIdx.z;
    int k0 = blockIdx.y * 32, c0 = blockIdx.x * 32;
    const float* W = (j < RREL) ? Wr + (size_t)j * KDIM * dob : Wo;
    for (int r = threadIdx.y; r < 32; r += 8)
        t[r][threadIdx.x] = W[(size_t)(k0 + r) * dob + c0 + threadIdx.x];
    __syncthreads();
    for (int r = threadIdx.y; r < 32; r += 8) {
        int n = j * dob + c0 + r;
        g_wcat[(size_t)n * KDIM + k0 + threadIdx.x] = tf32_rn(t[threadIdx.x][r]);
    }
}
__global__ void k_round(const float* __restrict__ in, float* __restrict__ out, int n4) {
    int i = blockIdx.x * blockDim.x + threadIdx.x;
    if (i >= n4) return;
    float4 v = ((const float4*)in)[i];
    v.x = tf32_rn(v.x); v.y = tf32_rn(v.y); v.z = tf32_rn(v.z); v.w = tf32_rn(v.w);
    ((float4*)out)[i] = v;
}

// ---------------- tf32 mma.sync GEMM + fused attention-dot epilogue ----------------
// C[M,Nc] = A[M,256] * g_wcat^T; also atomically accumulates s = row·att into g_sc.
__global__ __launch_bounds__(256, 2)
void k_mma(const float* __restrict__ A, float* __restrict__ C, int M, int Nc, int dob,
           const float* __restrict__ asrc, const float* __restrict__ adst) {
    extern __shared__ float sm[];
    float* sA[2] = { sm,                    sm + CHUNK_FLOATS };
    float* sB[2] = { sm + 2 * CHUNK_FLOATS, sm + 3 * CHUNK_FLOATS };

    int tid  = threadIdx.x;
    int wid  = tid >> 5, lane = tid & 31;
    int wm   = wid >> 1;
    int wn   = wid & 1;
    int bm   = blockIdx.y * BM, bn = blockIdx.x * BN;
    int lq   = lane >> 2;
    int lr   = lane & 3;

    float acc[2][8][4];
#pragma unroll
    for (int mt = 0; mt < 2; mt++)
#pragma unroll
        for (int nt = 0; nt < 8; nt++)
#pragma unroll
            for (int i = 0; i < 4; i++) acc[mt][nt][i] = 0.f;

    uint32_t sAb[2] = { smem_u32(sA[0]), smem_u32(sA[1]) };
    uint32_t sBb[2] = { smem_u32(sB[0]), smem_u32(sB[1]) };

    int lrow = tid >> 3;
    int lc4  = (tid & 7) * 4;

    auto load_chunk = [&](int buf, int kc) {
        int c0 = kc * KC;
#pragma unroll
        for (int it = 0; it < 4; it++) {
            int r = lrow + it * 32;
            uint32_t off = (uint32_t)(r * ASTRIDE + lc4) * 4u;
            const float* ga = A + (size_t)(bm + r) * KDIM + c0 + lc4;
            cp_async16(sAb[buf] + off, ga, (bm + r < M) ? 16 : 0);
            const float* gb = g_wcat + (size_t)(bn + r) * KDIM + c0 + lc4;
            cp_async16(sBb[buf] + off, gb, 16);
        }
        asm volatile("cp.async.commit_group;" ::: "memory");
    };

    load_chunk(0, 0);

    for (int kc = 0; kc < NKC; kc++) {
        int buf = kc & 1;
        if (kc + 1 < NKC) {
            load_chunk(buf ^ 1, kc + 1);
            asm volatile("cp.async.wait_group 1;" ::: "memory");
        } else {
            asm volatile("cp.async.wait_group 0;" ::: "memory");
        }
        __syncthreads();

        const float* a_s = sA[buf];
        const float* b_s = sB[buf];
#pragma unroll
        for (int k8 = 0; k8 < KC / 8; k8++) {
            int kb = k8 * 8 + lr;
            float afr[2][4];
#pragma unroll
            for (int mt = 0; mt < 2; mt++) {
                int r0 = wm * 32 + mt * 16 + lq;
                afr[mt][0] = a_s[r0 * ASTRIDE + kb];
                afr[mt][1] = a_s[(r0 + 8) * ASTRIDE + kb];
                afr[mt][2] = a_s[r0 * ASTRIDE + kb + 4];
                afr[mt][3] = a_s[(r0 + 8) * ASTRIDE + kb + 4];
            }
            float bfr[8][2];
#pragma unroll
            for (int nt = 0; nt < 8; nt++) {
                int n0 = wn * 64 + nt * 8 + lq;
                bfr[nt][0] = b_s[n0 * ASTRIDE + kb];
                bfr[nt][1] = b_s[n0 * ASTRIDE + kb + 4];
            }
#pragma unroll
            for (int mt = 0; mt < 2; mt++)
#pragma unroll
                for (int nt = 0; nt < 8; nt++)
                    mma_tf32(acc[mt][nt][0], acc[mt][nt][1], acc[mt][nt][2], acc[mt][nt][3],
                             afr[mt][0], afr[mt][1], afr[mt][2], afr[mt][3],
                             bfr[nt][0], bfr[nt][1]);
        }
        __syncthreads();
    }

    // att segment for this CTA's column block
    int j    = bn / dob;                  // relation slot (8 = root)
    int cbas = bn - j * dob;              // offset of this CTA inside the j block
    const float* att = (j < RREL) ? asrc : adst;

#pragma unroll
    for (int mt = 0; mt < 2; mt++) {
        int r0 = bm + wm * 32 + mt * 16 + lq;
        float s0 = 0.f, s1 = 0.f;
#pragma unroll
        for (int nt = 0; nt < 8; nt++) {
            int col = wn * 64 + nt * 8 + 2 * lr;
            float a0 = att[cbas + col], a1 = att[cbas + col + 1];
            s0 += acc[mt][nt][0] * a0 + acc[mt][nt][1] * a1;
            s1 += acc[mt][nt][2] * a0 + acc[mt][nt][3] * a1;
            int gcol = bn + col;
            if (r0 < M)
                *(float2*)(C + (size_t)r0 * Nc + gcol) =
                    make_float2(acc[mt][nt][0], acc[mt][nt][1]);
            if (r0 + 8 < M)
                *(float2*)(C + (size_t)(r0 + 8) * Nc + gcol) =
                    make_float2(acc[mt][nt][2], acc[mt][nt][3]);
        }
        // reduce partial dots across the 4-lane quad (same rows, different cols)
        s0 += __shfl_xor_sync(0xffffffffu, s0, 1);
        s0 += __shfl_xor_sync(0xffffffffu, s0, 2);
        s1 += __shfl_xor_sync(0xffffffffu, s1, 1);
        s1 += __shfl_xor_sync(0xffffffffu, s1, 2);
        if (lr == 0) {
            if (r0 < M)     atomicAdd(&g_sc[r0 * 9 + j], s0);
            if (r0 + 8 < M) atomicAdd(&g_sc[(r0 + 8) * 9 + j], s1);
        }
    }
}

// ---------------- edge scores ----------------
__global__ void k_score(const int* __restrict__ src, const int* __restrict__ dst,
                        const int* __restrict__ et, int E) {
    int e = blockIdx.x * blockDim.x + threadIdx.x;
    if (e >= E) return;
    float s = g_sc[src[e] * 9 + et[e]] + g_sc[dst[e] * 9 + 8];
    g_score[e] = (s > 0.f) ? s : 0.2f * s;
}

// ---------------- warp-per-node softmax aggregation + epilogue ----------------
// NV=2 (dob=256, hidden): h_out = h_in + relu(root+agg+relagg); art = tf32(h_out)
// NV=1 (dob=128, final):  h_out = root + agg
template <int NV>
__global__ void k_agg(const float* __restrict__ hr, const int* __restrict__ src,
                      const int* __restrict__ et, const float* __restrict__ h_in,
                      float* __restrict__ h_out, float* __restrict__ art, int n) {
    int gw = (blockIdx.x * blockDim.x + threadIdx.x) >> 5;
    int lane = threadIdx.x & 31;
    if (gw >= n) return;
    const int dob = NV * 128;
    const int pitch = 9 * dob;
    int node = gw;
    int beg = g_rowptr[node];
    int deg = g_rowptr[node + 1] - beg;

    float4 acc0 = make_float4(0.f, 0.f, 0.f, 0.f);
    float4 acc1 = make_float4(0.f, 0.f, 0.f, 0.f);

    if (deg > 0) {
        float m = -1e30f;
        for (int i = lane; i < deg; i += 32)
            m = fmaxf(m, g_score[g_eidx[beg + i]]);
#pragma unroll
        for (int o = 16; o; o >>= 1) m = fmaxf(m, __shfl_xor_sync(0xffffffffu, m, o));

        float dsum = 0.f;
        for (int base = 0; base < deg; base += 32) {
            int i = base + lane;
            float wv = 0.f; int rb = 0;
            if (i < deg) {
                int e = g_eidx[beg + i];
                wv = __expf(g_score[e] - m);
                rb = src[e] * pitch + et[e] * dob;
            }
            dsum += wv;
            int cnt = min(32, deg - base);
            for (int jj = 0; jj < cnt; jj++) {
                float wj = __shfl_sync(0xffffffffu, wv, jj);
                int rbj  = __shfl_sync(0xffffffffu, rb, jj);
                const float4* p = (const float4*)(hr + rbj);
                float4 v = p[lane];
                acc0.x += wj * v.x; acc0.y += wj * v.y;
                acc0.z += wj * v.z; acc0.w += wj * v.w;
                if (NV == 2) {
                    float4 v2 = p[lane + 32];
                    acc1.x += wj * v2.x; acc1.y += wj * v2.y;
                    acc1.z += wj * v2.z; acc1.w += wj * v2.w;
                }
            }
        }
#pragma unroll
        for (int o = 16; o; o >>= 1) dsum += __shfl_xor_sync(0xffffffffu, dsum, o);
        float inv = 1.f / dsum;
        acc0.x *= inv; acc0.y *= inv; acc0.z *= inv; acc0.w *= inv;
        if (NV == 2) { acc1.x *= inv; acc1.y *= inv; acc1.z *= inv; acc1.w *= inv; }
    }

    const float4* rootp = (const float4*)(hr + (size_t)node * pitch + RREL * dob);
    if (NV == 1) {
        float4 r = rootp[lane];
        r.x += acc0.x; r.y += acc0.y; r.z += acc0.z; r.w += acc0.w;
        ((float4*)(h_out + (size_t)node * dob))[lane] = r;
    } else {
        const float4* rap = (const float4*)(g_relagg + (size_t)node * HDIM);
        const float4* hip = (const float4*)(h_in + (size_t)node * dob);
        float4* hop = (float4*)(h_out + (size_t)node * dob);
        float4* arp = (float4*)(art + (size_t)node * dob);
#pragma unroll
        for (int half = 0; half < 2; half++) {
            int li = lane + half * 32;
            float4 r = rootp[li], ra = rap[li], hi = hip[li];
            float4 a = half ? acc1 : acc0;
            float4 o;
            o.x = hi.x + fmaxf(r.x + a.x + ra.x, 0.f);
            o.y = hi.y + fmaxf(r.y + a.y + ra.y, 0.f);
            o.z = hi.z + fmaxf(r.z + a.z + ra.z, 0.f);
            o.w = hi.w + fmaxf(r.w + a.w + ra.w, 0.f);
            hop[li] = o;
            float4 t;
            t.x = tf32_rn(o.x); t.y = tf32_rn(o.y);
            t.z = tf32_rn(o.z); t.w = tf32_rn(o.w);
            arp[li] = t;
        }
    }
}

// ---------------- launcher ----------------
extern "C" void kernel_launch(void* const* d_in, const int* in_sizes, int n_in,
                              void* d_out, int out_size) {
    const float* x    = (const float*)d_in[0];
    const int*   ei   = (const int*)  d_in[1];
    const int*   et   = (const int*)  d_in[2];
    const float* remb = (const float*)d_in[3];
    const float* rpw  = (const float*)d_in[4];
    const float* rpb  = (const float*)d_in[5];
    const float* Wr[3] = {(const float*)d_in[6],  (const float*)d_in[10], (const float*)d_in[14]};
    const float* Wo[3] = {(const float*)d_in[7],  (const float*)d_in[11], (const float*)d_in[15]};
    const float* Av[3] = {(const float*)d_in[8],  (const float*)d_in[12], (const float*)d_in[16]};
    const float* Ad[3] = {(const float*)d_in[9],  (const float*)d_in[13], (const float*)d_in[17]};

    int N = in_sizes[0] / HDIM;     // 20000
    int E = in_sizes[2];            // 400000
    const int* srcp = ei;
    const int* dstp = ei + E;

    float *hr, *h1, *h2, *art;
    cudaGetSymbolAddress((void**)&hr,  g_hr);
    cudaGetSymbolAddress((void**)&h1,  g_h1);
    cudaGetSymbolAddress((void**)&h2,  g_h2);
    cudaGetSymbolAddress((void**)&art, g_art);

    cudaFuncSetAttribute(k_mma, cudaFuncAttributeMaxDynamicSharedMemorySize, SMEM_BYTES);

    // ---- graph prep (layer-invariant) ----
    k_zero<<<(NMAX * RREL + 255) / 256, 256>>>();
    k_degcnt<<<(E + 255) / 256, 256>>>(dstp, et, E);
    k_scan<<<1, 1024>>>(N);
    k_fill<<<(E + 255) / 256, 256>>>(dstp, E);
    k_projrel<<<RREL, HDIM>>>(remb, rpw, rpb);
    k_relagg<<<N, HDIM>>>();
    int n4 = N * HDIM / 4;
    k_round<<<(n4 + 255) / 256, 256>>>(x, art, n4);   // tf32-round layer-0 input once

    // ---- three RGAT layers ----
    const float* hin = x;
    for (int l = 0; l < 3; l++) {
        int dob = (l == 2) ? ODIM : HDIM;
        int pitch = 9 * dob;

        dim3 gt(dob / 32, KDIM / 32, 9);
        k_repackT<<<gt, dim3(32, 8)>>>(Wr[l], Wo[l], dob);
        k_zsc<<<(N * 9 + 255) / 256, 256>>>(N * 9);

        dim3 g(pitch / BN, (N + BM - 1) / BM);
        k_mma<<<g, 256, SMEM_BYTES>>>(art, hr, N, pitch, dob, Av[l], Ad[l]);

        k_score<<<(E + 255) / 256, 256>>>(srcp, dstp, et, E);

        float* hout = (l == 0) ? h1 : (l == 1) ? h2 : (float*)d_out;
        int wblocks = (N * 32 + 255) / 256;
        if (l == 2)
            k_agg<1><<<wblocks, 256>>>(hr, srcp, et, hin, hout, art, N);
        else
            k_agg<2><<<wblocks, 256>>>(hr, srcp, et, hin, hout, art, N);
        hin = hout;
    }
}

// round 10
// speedup vs baseline: 3.1289x; 1.2858x over previous
#include <cuda_runtime.h>
#include <cuda_fp16.h>
#include <cstdint>
#include <math.h>

// ---------------- problem constants ----------------
#define NMAX   20000
#define EMAX   400000
#define RREL   8
#define HDIM   256
#define ODIM   128
#define PITCH0 (9*HDIM)   // 2304

// GEMM tiling (fp16 mma m16n8k16)
#define BM 128
#define BN 128
#define KDIM 256
#define KC 32                    // K halves per smem chunk (= 64 B/row)
#define NKC (KDIM/KC)            // 8 chunks
#define HSTRIDE 40               // padded smem row stride in halves (conflict-free)
#define CHUNK_H (128*HSTRIDE)
#define SMEM_BYTES (4*CHUNK_H*2) // A0,A1,B0,B1 = 40960 B

// ---------------- static scratch ----------------
__device__ __align__(16) float  g_hr[(size_t)NMAX * PITCH0];
__device__ __align__(16) float  g_h1[(size_t)NMAX * HDIM];
__device__ __align__(16) float  g_h2[(size_t)NMAX * HDIM];
__device__ __align__(16) __half g_arth[(size_t)NMAX * HDIM];   // fp16 activations (GEMM A)
__device__ __align__(16) float  g_relagg[(size_t)NMAX * HDIM];
__device__ __align__(16) __half g_wcat[(size_t)PITCH0 * KDIM]; // B K-major fp16
__device__ float g_projrel[RREL * HDIM];
__device__ float g_sc[NMAX * 9];
__device__ float g_score[EMAX];    // CSR-ordered
__device__ int   g_rb[EMAX];       // CSR-ordered gather row base
__device__ int   g_deg[NMAX];
__device__ int   g_rowptr[NMAX + 1];
__device__ int   g_cursor[NMAX];
__device__ int   g_eidx[EMAX];
__device__ int   g_cnt[NMAX * RREL];

// ---------------- helpers ----------------
__device__ __forceinline__ uint32_t smem_u32(const void* p) {
    uint32_t a;
    asm("{ .reg .u64 t; cvta.to.shared.u64 t, %1; cvt.u32.u64 %0, t; }" : "=r"(a) : "l"(p));
    return a;
}
__device__ __forceinline__ void cp_async16(uint32_t dst, const void* src, int src_sz) {
    asm volatile("cp.async.ca.shared.global [%0], [%1], 16, %2;"
                 :: "r"(dst), "l"(src), "r"(src_sz) : "memory");
}
__device__ __forceinline__ void mma_f16(float& d0, float& d1, float& d2, float& d3,
                                        uint32_t a0, uint32_t a1, uint32_t a2, uint32_t a3,
                                        uint32_t b0, uint32_t b1) {
    asm volatile(
        "mma.sync.aligned.m16n8k16.row.col.f32.f16.f16.f32 "
        "{%0,%1,%2,%3}, {%4,%5,%6,%7}, {%8,%9}, {%0,%1,%2,%3};"
        : "+f"(d0), "+f"(d1), "+f"(d2), "+f"(d3)
        : "r"(a0), "r"(a1), "r"(a2), "r"(a3), "r"(b0), "r"(b1));
}

// ---------------- prep kernels ----------------
__global__ void k_zero() {
    int i = blockIdx.x * blockDim.x + threadIdx.x;
    if (i < NMAX) g_deg[i] = 0;
    if (i < NMAX * RREL) g_cnt[i] = 0;
}
__global__ void k_zsc(int n9) {
    int i = blockIdx.x * blockDim.x + threadIdx.x;
    if (i < n9) g_sc[i] = 0.f;
}
__global__ void k_degcnt(const int* __restrict__ dst, const int* __restrict__ et, int E) {
    int e = blockIdx.x * blockDim.x + threadIdx.x;
    if (e < E) {
        int d = dst[e];
        atomicAdd(&g_deg[d], 1);
        atomicAdd(&g_cnt[d * RREL + et[e]], 1);
    }
}
__global__ void k_scan(int n) {
    __shared__ int part[1024];
    int t = threadIdx.x;
    int per = (n + 1023) >> 10;
    int base = t * per;
    int s = 0;
    for (int i = 0; i < per; i++) { int idx = base + i; if (idx < n) s += g_deg[idx]; }
    part[t] = s; __syncthreads();
    for (int off = 1; off < 1024; off <<= 1) {
        int v = (t >= off) ? part[t - off] : 0;
        __syncthreads(); part[t] += v; __syncthreads();
    }
    int run = (t > 0) ? part[t - 1] : 0;
    for (int i = 0; i < per; i++) {
        int idx = base + i;
        if (idx < n) { g_rowptr[idx] = run; g_cursor[idx] = run; run += g_deg[idx]; }
    }
    if (t == 1023) g_rowptr[n] = part[1023];
}
__global__ void k_fill(const int* __restrict__ dst, int E) {
    int e = blockIdx.x * blockDim.x + threadIdx.x;
    if (e < E) {
        int p = atomicAdd(&g_cursor[dst[e]], 1);
        g_eidx[p] = e;
    }
}
__global__ void k_projrel(const float* __restrict__ re, const float* __restrict__ w,
                          const float* __restrict__ b) {
    int r = blockIdx.x, c = threadIdx.x;
    float s = b[c];
    for (int k = 0; k < HDIM; k++) s += re[r * HDIM + k] * w[k * HDIM + c];
    g_projrel[r * HDIM + c] = s;
}
__global__ void k_relagg() {
    int node = blockIdx.x, c = threadIdx.x;
    __shared__ float cc[RREL];
    if (c < RREL) cc[c] = (float)g_cnt[node * RREL + c];
    __syncthreads();
    float s = 0.f;
#pragma unroll
    for (int r = 0; r < RREL; r++) s += cc[r] * g_projrel[r * HDIM + c];
    g_relagg[(size_t)node * HDIM + c] = s;
}
// transpose weights K-major fp16: g_wcat[n*256 + k] = h(W[k][n]), n = j*dob + c
__global__ void k_repackT(const float* __restrict__ Wr, const float* __restrict__ Wo, int dob) {
    __shared__ float t[32][33];
    int j = blockIdx.z;
    int k0 = blockIdx.y * 32, c0 = blockIdx.x * 32;
    const float* W = (j < RREL) ? Wr + (size_t)j * KDIM * dob : Wo;
    for (int r = threadIdx.y; r < 32; r += 8)
        t[r][threadIdx.x] = W[(size_t)(k0 + r) * dob + c0 + threadIdx.x];
    __syncthreads();
    for (int r = threadIdx.y; r < 32; r += 8) {
        int n = j * dob + c0 + r;
        g_wcat[(size_t)n * KDIM + k0 + threadIdx.x] = __float2half_rn(t[threadIdx.x][r]);
    }
}
__global__ void k_tohalf(const float* __restrict__ in, __half* __restrict__ out, int n4) {
    int i = blockIdx.x * blockDim.x + threadIdx.x;
    if (i >= n4) return;
    float4 v = ((const float4*)in)[i];
    ((__half2*)out)[i * 2]     = __floats2half2_rn(v.x, v.y);
    ((__half2*)out)[i * 2 + 1] = __floats2half2_rn(v.z, v.w);
}

// ---------------- fp16 mma GEMM + fused attention-dot epilogue ----------------
__global__ __launch_bounds__(256, 2)
void k_mma(const __half* __restrict__ A, float* __restrict__ C, int M, int Nc, int dob,
           const float* __restrict__ asrc, const float* __restrict__ adst) {
    extern __shared__ __half sm[];
    __half* sA[2] = { sm,               sm + CHUNK_H };
    __half* sB[2] = { sm + 2 * CHUNK_H, sm + 3 * CHUNK_H };

    int tid  = threadIdx.x;
    int wid  = tid >> 5, lane = tid & 31;
    int wm   = wid >> 1;
    int wn   = wid & 1;
    int bm   = blockIdx.y * BM, bn = blockIdx.x * BN;
    int lq   = lane >> 2;
    int lr   = lane & 3;

    float acc[2][8][4];
#pragma unroll
    for (int mt = 0; mt < 2; mt++)
#pragma unroll
        for (int nt = 0; nt < 8; nt++)
#pragma unroll
            for (int i = 0; i < 4; i++) acc[mt][nt][i] = 0.f;

    uint32_t sAb[2] = { smem_u32(sA[0]), smem_u32(sA[1]) };
    uint32_t sBb[2] = { smem_u32(sB[0]), smem_u32(sB[1]) };

    // chunk = 128 rows x 32 halves (64 B/row) = 8192 B per tile.
    // 2 threads per row; each thread issues TWO 16B cp.asyncs per tile:
    // segments lseg and lseg+8 (halves), lseg = (tid&1)*16.
    int lrow = tid >> 1;          // 0..127
    int lseg = (tid & 1) * 16;    // 0 or 16 halves

    auto load_chunk = [&](int buf, int kc) {
        int c0 = kc * KC;
        int asz = (bm + lrow < M) ? 16 : 0;
        const __half* ga = A + (size_t)(bm + lrow) * KDIM + c0 + lseg;
        const __half* gb = g_wcat + (size_t)(bn + lrow) * KDIM + c0 + lseg;
        uint32_t off = (uint32_t)(lrow * HSTRIDE + lseg) * 2u;
        cp_async16(sAb[buf] + off,      ga,     asz);
        cp_async16(sAb[buf] + off + 16, ga + 8, asz);
        cp_async16(sBb[buf] + off,      gb,     16);
        cp_async16(sBb[buf] + off + 16, gb + 8, 16);
        asm volatile("cp.async.commit_group;" ::: "memory");
    };

    load_chunk(0, 0);

    for (int kc = 0; kc < NKC; kc++) {
        int buf = kc & 1;
        if (kc + 1 < NKC) {
            load_chunk(buf ^ 1, kc + 1);
            asm volatile("cp.async.wait_group 1;" ::: "memory");
        } else {
            asm volatile("cp.async.wait_group 0;" ::: "memory");
        }
        __syncthreads();

        const __half* a_s = sA[buf];
        const __half* b_s = sB[buf];
#pragma unroll
        for (int ks = 0; ks < 2; ks++) {
            int kb = ks * 16 + 2 * lr;
            uint32_t afr[2][4];
#pragma unroll
            for (int mt = 0; mt < 2; mt++) {
                int r0 = wm * 32 + mt * 16 + lq;
                afr[mt][0] = *(const uint32_t*)(a_s + r0 * HSTRIDE + kb);
                afr[mt][1] = *(const uint32_t*)(a_s + (r0 + 8) * HSTRIDE + kb);
                afr[mt][2] = *(const uint32_t*)(a_s + r0 * HSTRIDE + kb + 8);
                afr[mt][3] = *(const uint32_t*)(a_s + (r0 + 8) * HSTRIDE + kb + 8);
            }
            uint32_t bfr[8][2];
#pragma unroll
            for (int nt = 0; nt < 8; nt++) {
                int n0 = wn * 64 + nt * 8 + lq;
                bfr[nt][0] = *(const uint32_t*)(b_s + n0 * HSTRIDE + kb);
                bfr[nt][1] = *(const uint32_t*)(b_s + n0 * HSTRIDE + kb + 8);
            }
#pragma unroll
            for (int mt = 0; mt < 2; mt++)
#pragma unroll
                for (int nt = 0; nt < 8; nt++)
                    mma_f16(acc[mt][nt][0], acc[mt][nt][1], acc[mt][nt][2], acc[mt][nt][3],
                            afr[mt][0], afr[mt][1], afr[mt][2], afr[mt][3],
                            bfr[nt][0], bfr[nt][1]);
        }
        __syncthreads();
    }

    // fused attention-dot + store
    int j    = bn / dob;               // relation slot (8 = root)
    int cbas = bn - j * dob;
    const float* att = (j < RREL) ? asrc : adst;

#pragma unroll
    for (int mt = 0; mt < 2; mt++) {
        int r0 = bm + wm * 32 + mt * 16 + lq;
        float s0 = 0.f, s1 = 0.f;
#pragma unroll
        for (int nt = 0; nt < 8; nt++) {
            int col = wn * 64 + nt * 8 + 2 * lr;
            float a0 = att[cbas + col], a1 = att[cbas + col + 1];
            s0 += acc[mt][nt][0] * a0 + acc[mt][nt][1] * a1;
            s1 += acc[mt][nt][2] * a0 + acc[mt][nt][3] * a1;
            int gcol = bn + col;
            if (r0 < M)
                *(float2*)(C + (size_t)r0 * Nc + gcol) =
                    make_float2(acc[mt][nt][0], acc[mt][nt][1]);
            if (r0 + 8 < M)
                *(float2*)(C + (size_t)(r0 + 8) * Nc + gcol) =
                    make_float2(acc[mt][nt][2], acc[mt][nt][3]);
        }
        s0 += __shfl_xor_sync(0xffffffffu, s0, 1);
        s0 += __shfl_xor_sync(0xffffffffu, s0, 2);
        s1 += __shfl_xor_sync(0xffffffffu, s1, 1);
        s1 += __shfl_xor_sync(0xffffffffu, s1, 2);
        if (lr == 0) {
            if (r0 < M)     atomicAdd(&g_sc[r0 * 9 + j], s0);
            if (r0 + 8 < M) atomicAdd(&g_sc[(r0 + 8) * 9 + j], s1);
        }
    }
}

// ---------------- edge scores, CSR-ordered ----------------
__global__ void k_score(const int* __restrict__ src, const int* __restrict__ dst,
                        const int* __restrict__ et, int E, int pitch, int dob) {
    int p = blockIdx.x * blockDim.x + threadIdx.x;
    if (p >= E) return;
    int e  = g_eidx[p];
    int s_ = src[e], d_ = dst[e], t_ = et[e];
    float s = g_sc[s_ * 9 + t_] + g_sc[d_ * 9 + 8];
    g_score[p] = (s > 0.f) ? s : 0.2f * s;
    g_rb[p]    = s_ * pitch + t_ * dob;
}

// ---------------- warp-per-node softmax aggregation + epilogue ----------------
template <int NV>
__global__ void k_agg(const float* __restrict__ hr, const float* __restrict__ h_in,
                      float* __restrict__ h_out, __half* __restrict__ arth, int n) {
    int gw = (blockIdx.x * blockDim.x + threadIdx.x) >> 5;
    int lane = threadIdx.x & 31;
    if (gw >= n) return;
    const int dob = NV * 128;
    const int pitch = 9 * dob;
    int node = gw;
    int beg = g_rowptr[node];
    int deg = g_rowptr[node + 1] - beg;

    float4 acc0 = make_float4(0.f, 0.f, 0.f, 0.f);
    float4 acc1 = make_float4(0.f, 0.f, 0.f, 0.f);

    if (deg > 0) {
        float m = -1e30f;
        for (int i = lane; i < deg; i += 32)
            m = fmaxf(m, g_score[beg + i]);
#pragma unroll
        for (int o = 16; o; o >>= 1) m = fmaxf(m, __shfl_xor_sync(0xffffffffu, m, o));

        float dsum = 0.f;
        for (int base = 0; base < deg; base += 32) {
            int i = base + lane;
            float wv = 0.f; int rb = 0;
            if (i < deg) {
                wv = __expf(g_score[beg + i] - m);
                rb = g_rb[beg + i];
            }
            dsum += wv;
            int cnt = min(32, deg - base);
            for (int jj = 0; jj < cnt; jj++) {
                float wj = __shfl_sync(0xffffffffu, wv, jj);
                int rbj  = __shfl_sync(0xffffffffu, rb, jj);
                const float4* p = (const float4*)(hr + rbj);
                float4 v = p[lane];
                acc0.x += wj * v.x; acc0.y += wj * v.y;
                acc0.z += wj * v.z; acc0.w += wj * v.w;
                if (NV == 2) {
                    float4 v2 = p[lane + 32];
                    acc1.x += wj * v2.x; acc1.y += wj * v2.y;
                    acc1.z += wj * v2.z; acc1.w += wj * v2.w;
                }
            }
        }
#pragma unroll
        for (int o = 16; o; o >>= 1) dsum += __shfl_xor_sync(0xffffffffu, dsum, o);
        float inv = 1.f / dsum;
        acc0.x *= inv; acc0.y *= inv; acc0.z *= inv; acc0.w *= inv;
        if (NV == 2) { acc1.x *= inv; acc1.y *= inv; acc1.z *= inv; acc1.w *= inv; }
    }

    const float4* rootp = (const float4*)(hr + (size_t)node * pitch + RREL * dob);
    if (NV == 1) {
        float4 r = rootp[lane];
        r.x += acc0.x; r.y += acc0.y; r.z += acc0.z; r.w += acc0.w;
        ((float4*)(h_out + (size_t)node * dob))[lane] = r;
    } else {
        const float4* rap = (const float4*)(g_relagg + (size_t)node * HDIM);
        const float4* hip = (const float4*)(h_in + (size_t)node * dob);
        float4* hop = (float4*)(h_out + (size_t)node * dob);
        __half2* arp = (__half2*)(arth + (size_t)node * dob);
#pragma unroll
        for (int half = 0; half < 2; half++) {
            int li = lane + half * 32;
            float4 r = rootp[li], ra = rap[li], hi = hip[li];
            float4 a = half ? acc1 : acc0;
            float4 o;
            o.x = hi.x + fmaxf(r.x + a.x + ra.x, 0.f);
            o.y = hi.y + fmaxf(r.y + a.y + ra.y, 0.f);
            o.z = hi.z + fmaxf(r.z + a.z + ra.z, 0.f);
            o.w = hi.w + fmaxf(r.w + a.w + ra.w, 0.f);
            hop[li] = o;
            arp[li * 2]     = __floats2half2_rn(o.x, o.y);
            arp[li * 2 + 1] = __floats2half2_rn(o.z, o.w);
        }
    }
}

// ---------------- launcher ----------------
extern "C" void kernel_launch(void* const* d_in, const int* in_sizes, int n_in,
                              void* d_out, int out_size) {
    const float* x    = (const float*)d_in[0];
    const int*   ei   = (const int*)  d_in[1];
    const int*   et   = (const int*)  d_in[2];
    const float* remb = (const float*)d_in[3];
    const float* rpw  = (const float*)d_in[4];
    const float* rpb  = (const float*)d_in[5];
    const float* Wr[3] = {(const float*)d_in[6],  (const float*)d_in[10], (const float*)d_in[14]};
    const float* Wo[3] = {(const float*)d_in[7],  (const float*)d_in[11], (const float*)d_in[15]};
    const float* Av[3] = {(const float*)d_in[8],  (const float*)d_in[12], (const float*)d_in[16]};
    const float* Ad[3] = {(const float*)d_in[9],  (const float*)d_in[13], (const float*)d_in[17]};

    int N = in_sizes[0] / HDIM;     // 20000
    int E = in_sizes[2];            // 400000
    const int* srcp = ei;
    const int* dstp = ei + E;

    float *hr, *h1, *h2;
    __half* arth;
    cudaGetSymbolAddress((void**)&hr,   g_hr);
    cudaGetSymbolAddress((void**)&h1,   g_h1);
    cudaGetSymbolAddress((void**)&h2,   g_h2);
    cudaGetSymbolAddress((void**)&arth, g_arth);

    cudaFuncSetAttribute(k_mma, cudaFuncAttributeMaxDynamicSharedMemorySize, SMEM_BYTES);

    // ---- graph prep (layer-invariant) ----
    k_zero<<<(NMAX * RREL + 255) / 256, 256>>>();
    k_degcnt<<<(E + 255) / 256, 256>>>(dstp, et, E);
    k_scan<<<1, 1024>>>(N);
    k_fill<<<(E + 255) / 256, 256>>>(dstp, E);
    k_projrel<<<RREL, HDIM>>>(remb, rpw, rpb);
    k_relagg<<<N, HDIM>>>();
    int n4 = N * HDIM / 4;
    k_tohalf<<<(n4 + 255) / 256, 256>>>(x, arth, n4);

    // ---- three RGAT layers ----
    const float* hin = x;
    for (int l = 0; l < 3; l++) {
        int dob = (l == 2) ? ODIM : HDIM;
        int pitch = 9 * dob;

        dim3 gt(dob / 32, KDIM / 32, 9);
        k_repackT<<<gt, dim3(32, 8)>>>(Wr[l], Wo[l], dob);
        k_zsc<<<(N * 9 + 255) / 256, 256>>>(N * 9);

        dim3 g(pitch / BN, (N + BM - 1) / BM);
        k_mma<<<g, 256, SMEM_BYTES>>>(arth, hr, N, pitch, dob, Av[l], Ad[l]);

        k_score<<<(E + 255) / 256, 256>>>(srcp, dstp, et, E, pitch, dob);

        float* hout = (l == 0) ? h1 : (l == 1) ? h2 : (float*)d_out;
        int wblocks = (N * 32 + 255) / 256;
        if (l == 2)
            k_agg<1><<<wblocks, 256>>>(hr, hin, hout, arth, N);
        else
            k_agg<2><<<wblocks, 256>>>(hr, hin, hout, arth, N);
        hin = hout;
    }
}

// round 11
// speedup vs baseline: 3.4129x; 1.0908x over previous
#include <cuda_runtime.h>
#include <cuda_fp16.h>
#include <cstdint>
#include <math.h>

// ---------------- problem constants ----------------
#define NMAX   20000
#define EMAX   400000
#define RREL   8
#define HDIM   256
#define ODIM   128

// GEMM tiling (fp16 mma m16n8k16)
#define BM 128
#define BN 128
#define KDIM 256
#define KC 32                    // K halves per smem chunk (= 64 B/row)
#define NKC (KDIM/KC)            // 8 chunks
#define HSTRIDE 40               // padded smem row stride in halves (conflict-free)
#define CHUNK_H (128*HSTRIDE)
#define SMEM_BYTES (4*CHUNK_H*2) // A0,A1,B0,B1 = 40960 B

// ---------------- static scratch ----------------
__device__ __align__(16) __half g_hrh[(size_t)NMAX * RREL * HDIM];  // relation blocks, fp16
__device__ __align__(16) float  g_root[(size_t)NMAX * HDIM];        // root block, fp32
__device__ __align__(16) float  g_h1[(size_t)NMAX * HDIM];
__device__ __align__(16) float  g_h2[(size_t)NMAX * HDIM];
__device__ __align__(16) __half g_arth[(size_t)NMAX * HDIM];        // fp16 activations (GEMM A)
__device__ __align__(16) float  g_relagg[(size_t)NMAX * HDIM];
__device__ __align__(16) __half g_wcat[(size_t)(9*HDIM) * KDIM];    // B K-major fp16
__device__ float g_projrel[RREL * HDIM];
__device__ float g_sc[NMAX * 9];
__device__ float g_score[EMAX];    // CSR-ordered
__device__ int   g_rb[EMAX];       // CSR-ordered gather base (halves into g_hrh)
__device__ int   g_deg[NMAX];
__device__ int   g_rowptr[NMAX + 1];
__device__ int   g_cursor[NMAX];
__device__ int   g_eidx[EMAX];
__device__ int   g_cnt[NMAX * RREL];

// ---------------- helpers ----------------
__device__ __forceinline__ uint32_t smem_u32(const void* p) {
    uint32_t a;
    asm("{ .reg .u64 t; cvta.to.shared.u64 t, %1; cvt.u32.u64 %0, t; }" : "=r"(a) : "l"(p));
    return a;
}
__device__ __forceinline__ void cp_async16(uint32_t dst, const void* src, int src_sz) {
    asm volatile("cp.async.ca.shared.global [%0], [%1], 16, %2;"
                 :: "r"(dst), "l"(src), "r"(src_sz) : "memory");
}
__device__ __forceinline__ void mma_f16(float& d0, float& d1, float& d2, float& d3,
                                        uint32_t a0, uint32_t a1, uint32_t a2, uint32_t a3,
                                        uint32_t b0, uint32_t b1) {
    asm volatile(
        "mma.sync.aligned.m16n8k16.row.col.f32.f16.f16.f32 "
        "{%0,%1,%2,%3}, {%4,%5,%6,%7}, {%8,%9}, {%0,%1,%2,%3};"
        : "+f"(d0), "+f"(d1), "+f"(d2), "+f"(d3)
        : "r"(a0), "r"(a1), "r"(a2), "r"(a3), "r"(b0), "r"(b1));
}

// ---------------- prep kernels ----------------
__global__ void k_zero() {
    int i = blockIdx.x * blockDim.x + threadIdx.x;
    if (i < NMAX) g_deg[i] = 0;
    if (i < NMAX * RREL) g_cnt[i] = 0;
}
__global__ void k_zsc(int n9) {
    int i = blockIdx.x * blockDim.x + threadIdx.x;
    if (i < n9) g_sc[i] = 0.f;
}
__global__ void k_degcnt(const int* __restrict__ dst, const int* __restrict__ et, int E) {
    int e = blockIdx.x * blockDim.x + threadIdx.x;
    if (e < E) {
        int d = dst[e];
        atomicAdd(&g_deg[d], 1);
        atomicAdd(&g_cnt[d * RREL + et[e]], 1);
    }
}
__global__ void k_scan(int n) {
    __shared__ int part[1024];
    int t = threadIdx.x;
    int per = (n + 1023) >> 10;
    int base = t * per;
    int s = 0;
    for (int i = 0; i < per; i++) { int idx = base + i; if (idx < n) s += g_deg[idx]; }
    part[t] = s; __syncthreads();
    for (int off = 1; off < 1024; off <<= 1) {
        int v = (t >= off) ? part[t - off] : 0;
        __syncthreads(); part[t] += v; __syncthreads();
    }
    int run = (t > 0) ? part[t - 1] : 0;
    for (int i = 0; i < per; i++) {
        int idx = base + i;
        if (idx < n) { g_rowptr[idx] = run; g_cursor[idx] = run; run += g_deg[idx]; }
    }
    if (t == 1023) g_rowptr[n] = part[1023];
}
__global__ void k_fill(const int* __restrict__ dst, int E) {
    int e = blockIdx.x * blockDim.x + threadIdx.x;
    if (e < E) {
        int p = atomicAdd(&g_cursor[dst[e]], 1);
        g_eidx[p] = e;
    }
}
__global__ void k_projrel(const float* __restrict__ re, const float* __restrict__ w,
                          const float* __restrict__ b) {
    int r = blockIdx.x, c = threadIdx.x;
    float s = b[c];
    for (int k = 0; k < HDIM; k++) s += re[r * HDIM + k] * w[k * HDIM + c];
    g_projrel[r * HDIM + c] = s;
}
__global__ void k_relagg() {
    int node = blockIdx.x, c = threadIdx.x;
    __shared__ float cc[RREL];
    if (c < RREL) cc[c] = (float)g_cnt[node * RREL + c];
    __syncthreads();
    float s = 0.f;
#pragma unroll
    for (int r = 0; r < RREL; r++) s += cc[r] * g_projrel[r * HDIM + c];
    g_relagg[(size_t)node * HDIM + c] = s;
}
// transpose weights K-major fp16: g_wcat[n*256 + k] = h(W[k][n]), n = j*dob + c
__global__ void k_repackT(const float* __restrict__ Wr, const float* __restrict__ Wo, int dob) {
    __shared__ float t[32][33];
    int j = blockIdx.z;
    int k0 = blockIdx.y * 32, c0 = blockIdx.x * 32;
    const float* W = (j < RREL) ? Wr + (size_t)j * KDIM * dob : Wo;
    for (int r = threadIdx.y; r < 32; r += 8)
        t[r][threadIdx.x] = W[(size_t)(k0 + r) * dob + c0 + threadIdx.x];
    __syncthreads();
    for (int r = threadIdx.y; r < 32; r += 8) {
        int n = j * dob + c0 + r;
        g_wcat[(size_t)n * KDIM + k0 + threadIdx.x] = __float2half_rn(t[threadIdx.x][r]);
    }
}
__global__ void k_tohalf(const float* __restrict__ in, __half* __restrict__ out, int n4) {
    int i = blockIdx.x * blockDim.x + threadIdx.x;
    if (i >= n4) return;
    float4 v = ((const float4*)in)[i];
    ((__half2*)out)[i * 2]     = __floats2half2_rn(v.x, v.y);
    ((__half2*)out)[i * 2 + 1] = __floats2half2_rn(v.z, v.w);
}

// ---------------- fp16 mma GEMM + fused attention-dot + split fp16/fp32 store ----------------
__global__ __launch_bounds__(256, 2)
void k_mma(const __half* __restrict__ A, __half* __restrict__ Ch, float* __restrict__ Cr,
           int M, int dob,
           const float* __restrict__ asrc, const float* __restrict__ adst) {
    extern __shared__ __half sm[];
    __half* sA[2] = { sm,               sm + CHUNK_H };
    __half* sB[2] = { sm + 2 * CHUNK_H, sm + 3 * CHUNK_H };

    int tid  = threadIdx.x;
    int wid  = tid >> 5, lane = tid & 31;
    int wm   = wid >> 1;
    int wn   = wid & 1;
    int bm   = blockIdx.y * BM, bn = blockIdx.x * BN;
    int lq   = lane >> 2;
    int lr   = lane & 3;

    float acc[2][8][4];
#pragma unroll
    for (int mt = 0; mt < 2; mt++)
#pragma unroll
        for (int nt = 0; nt < 8; nt++)
#pragma unroll
            for (int i = 0; i < 4; i++) acc[mt][nt][i] = 0.f;

    uint32_t sAb[2] = { smem_u32(sA[0]), smem_u32(sA[1]) };
    uint32_t sBb[2] = { smem_u32(sB[0]), smem_u32(sB[1]) };

    int lrow = tid >> 1;          // 0..127
    int lseg = (tid & 1) * 16;    // 0 or 16 halves

    auto load_chunk = [&](int buf, int kc) {
        int c0 = kc * KC;
        int asz = (bm + lrow < M) ? 16 : 0;
        const __half* ga = A + (size_t)(bm + lrow) * KDIM + c0 + lseg;
        const __half* gb = g_wcat + (size_t)(bn + lrow) * KDIM + c0 + lseg;
        uint32_t off = (uint32_t)(lrow * HSTRIDE + lseg) * 2u;
        cp_async16(sAb[buf] + off,      ga,     asz);
        cp_async16(sAb[buf] + off + 16, ga + 8, asz);
        cp_async16(sBb[buf] + off,      gb,     16);
        cp_async16(sBb[buf] + off + 16, gb + 8, 16);
        asm volatile("cp.async.commit_group;" ::: "memory");
    };

    load_chunk(0, 0);

    for (int kc = 0; kc < NKC; kc++) {
        int buf = kc & 1;
        if (kc + 1 < NKC) {
            load_chunk(buf ^ 1, kc + 1);
            asm volatile("cp.async.wait_group 1;" ::: "memory");
        } else {
            asm volatile("cp.async.wait_group 0;" ::: "memory");
        }
        __syncthreads();

        const __half* a_s = sA[buf];
        const __half* b_s = sB[buf];
#pragma unroll
        for (int ks = 0; ks < 2; ks++) {
            int kb = ks * 16 + 2 * lr;
            uint32_t afr[2][4];
#pragma unroll
            for (int mt = 0; mt < 2; mt++) {
                int r0 = wm * 32 + mt * 16 + lq;
                afr[mt][0] = *(const uint32_t*)(a_s + r0 * HSTRIDE + kb);
                afr[mt][1] = *(const uint32_t*)(a_s + (r0 + 8) * HSTRIDE + kb);
                afr[mt][2] = *(const uint32_t*)(a_s + r0 * HSTRIDE + kb + 8);
                afr[mt][3] = *(const uint32_t*)(a_s + (r0 + 8) * HSTRIDE + kb + 8);
            }
            uint32_t bfr[8][2];
#pragma unroll
            for (int nt = 0; nt < 8; nt++) {
                int n0 = wn * 64 + nt * 8 + lq;
                bfr[nt][0] = *(const uint32_t*)(b_s + n0 * HSTRIDE + kb);
                bfr[nt][1] = *(const uint32_t*)(b_s + n0 * HSTRIDE + kb + 8);
            }
#pragma unroll
            for (int mt = 0; mt < 2; mt++)
#pragma unroll
                for (int nt = 0; nt < 8; nt++)
                    mma_f16(acc[mt][nt][0], acc[mt][nt][1], acc[mt][nt][2], acc[mt][nt][3],
                            afr[mt][0], afr[mt][1], afr[mt][2], afr[mt][3],
                            bfr[nt][0], bfr[nt][1]);
        }
        __syncthreads();
    }

    // fused attention-dot + split store
    int j    = bn / dob;               // relation slot (8 = root)
    int cbas = bn - j * dob;
    const float* att = (j < RREL) ? asrc : adst;
    bool isroot = (j >= RREL);

#pragma unroll
    for (int mt = 0; mt < 2; mt++) {
        int r0 = bm + wm * 32 + mt * 16 + lq;
        float s0 = 0.f, s1 = 0.f;
#pragma unroll
        for (int nt = 0; nt < 8; nt++) {
            int col = cbas + wn * 64 + nt * 8 + 2 * lr;
            float a0 = att[col], a1 = att[col + 1];
            s0 += acc[mt][nt][0] * a0 + acc[mt][nt][1] * a1;
            s1 += acc[mt][nt][2] * a0 + acc[mt][nt][3] * a1;
            if (isroot) {
                if (r0 < M)
                    *(float2*)(Cr + (size_t)r0 * dob + col) =
                        make_float2(acc[mt][nt][0], acc[mt][nt][1]);
                if (r0 + 8 < M)
                    *(float2*)(Cr + (size_t)(r0 + 8) * dob + col) =
                        make_float2(acc[mt][nt][2], acc[mt][nt][3]);
            } else {
                if (r0 < M)
                    *(__half2*)(Ch + ((size_t)r0 * RREL + j) * dob + col) =
                        __floats2half2_rn(acc[mt][nt][0], acc[mt][nt][1]);
                if (r0 + 8 < M)
                    *(__half2*)(Ch + ((size_t)(r0 + 8) * RREL + j) * dob + col) =
                        __floats2half2_rn(acc[mt][nt][2], acc[mt][nt][3]);
            }
        }
        s0 += __shfl_xor_sync(0xffffffffu, s0, 1);
        s0 += __shfl_xor_sync(0xffffffffu, s0, 2);
        s1 += __shfl_xor_sync(0xffffffffu, s1, 1);
        s1 += __shfl_xor_sync(0xffffffffu, s1, 2);
        if (lr == 0) {
            if (r0 < M)     atomicAdd(&g_sc[r0 * 9 + j], s0);
            if (r0 + 8 < M) atomicAdd(&g_sc[(r0 + 8) * 9 + j], s1);
        }
    }
}

// ---------------- edge scores, CSR-ordered ----------------
__global__ void k_score(const int* __restrict__ src, const int* __restrict__ dst,
                        const int* __restrict__ et, int E, int dob) {
    int p = blockIdx.x * blockDim.x + threadIdx.x;
    if (p >= E) return;
    int e  = g_eidx[p];
    int s_ = src[e], d_ = dst[e], t_ = et[e];
    float s = g_sc[s_ * 9 + t_] + g_sc[d_ * 9 + 8];
    g_score[p] = (s > 0.f) ? s : 0.2f * s;
    g_rb[p]    = (s_ * RREL + t_) * dob;   // halves offset into g_hrh
}

// ---------------- warp-per-node softmax aggregation + epilogue ----------------
// NV=2: dob=256, hidden layers. NV=1: dob=128, final layer.
template <int NV>
__global__ void k_agg(const __half* __restrict__ hrh, const float* __restrict__ root,
                      const float* __restrict__ h_in,
                      float* __restrict__ h_out, __half* __restrict__ arth, int n) {
    int gw = (blockIdx.x * blockDim.x + threadIdx.x) >> 5;
    int lane = threadIdx.x & 31;
    if (gw >= n) return;
    const int dob = NV * 128;
    int node = gw;
    int beg = g_rowptr[node];
    int deg = g_rowptr[node + 1] - beg;

    // lane covers columns [lane*4*NV, lane*4*NV + 4*NV)
    float accv[4 * NV];
#pragma unroll
    for (int i = 0; i < 4 * NV; i++) accv[i] = 0.f;

    if (deg > 0) {
        float m = -1e30f;
        for (int i = lane; i < deg; i += 32)
            m = fmaxf(m, g_score[beg + i]);
#pragma unroll
        for (int o = 16; o; o >>= 1) m = fmaxf(m, __shfl_xor_sync(0xffffffffu, m, o));

        float dsum = 0.f;
        for (int base = 0; base < deg; base += 32) {
            int i = base + lane;
            float wv = 0.f; int rb = 0;
            if (i < deg) {
                wv = __expf(g_score[beg + i] - m);
                rb = g_rb[beg + i];
            }
            dsum += wv;
            int cnt = min(32, deg - base);
            for (int jj = 0; jj < cnt; jj++) {
                float wj = __shfl_sync(0xffffffffu, wv, jj);
                int rbj  = __shfl_sync(0xffffffffu, rb, jj);
                if (NV == 2) {
                    uint4 v = ((const uint4*)(hrh + rbj))[lane];   // 8 halves
                    float2 f;
                    f = __half22float2(*(__half2*)&v.x); accv[0] += wj*f.x; accv[1] += wj*f.y;
                    f = __half22float2(*(__half2*)&v.y); accv[2] += wj*f.x; accv[3] += wj*f.y;
                    f = __half22float2(*(__half2*)&v.z); accv[4] += wj*f.x; accv[5] += wj*f.y;
                    f = __half22float2(*(__half2*)&v.w); accv[6] += wj*f.x; accv[7] += wj*f.y;
                } else {
                    uint2 v = ((const uint2*)(hrh + rbj))[lane];   // 4 halves
                    float2 f;
                    f = __half22float2(*(__half2*)&v.x); accv[0] += wj*f.x; accv[1] += wj*f.y;
                    f = __half22float2(*(__half2*)&v.y); accv[2] += wj*f.x; accv[3] += wj*f.y;
                }
            }
        }
#pragma unroll
        for (int o = 16; o; o >>= 1) dsum += __shfl_xor_sync(0xffffffffu, dsum, o);
        float inv = 1.f / dsum;
#pragma unroll
        for (int i = 0; i < 4 * NV; i++) accv[i] *= inv;
    }

    const float4* rootp = (const float4*)(root + (size_t)node * dob);
    if (NV == 1) {
        float4 r = rootp[lane];
        r.x += accv[0]; r.y += accv[1]; r.z += accv[2]; r.w += accv[3];
        ((float4*)(h_out + (size_t)node * dob))[lane] = r;
    } else {
        const float4* rap = (const float4*)(g_relagg + (size_t)node * HDIM);
        const float4* hip = (const float4*)(h_in + (size_t)node * dob);
        float4* hop = (float4*)(h_out + (size_t)node * dob);
        __half2* arp = (__half2*)(arth + (size_t)node * dob);
#pragma unroll
        for (int q = 0; q < 2; q++) {
            int li = lane * 2 + q;            // float4 index; columns li*4..+4
            float4 r = rootp[li], ra = rap[li], hi = hip[li];
            float4 o;
            o.x = hi.x + fmaxf(r.x + accv[q*4+0] + ra.x, 0.f);
            o.y = hi.y + fmaxf(r.y + accv[q*4+1] + ra.y, 0.f);
            o.z = hi.z + fmaxf(r.z + accv[q*4+2] + ra.z, 0.f);
            o.w = hi.w + fmaxf(r.w + accv[q*4+3] + ra.w, 0.f);
            hop[li] = o;
            arp[li * 2]     = __floats2half2_rn(o.x, o.y);
            arp[li * 2 + 1] = __floats2half2_rn(o.z, o.w);
        }
    }
}

// ---------------- launcher ----------------
extern "C" void kernel_launch(void* const* d_in, const int* in_sizes, int n_in,
                              void* d_out, int out_size) {
    const float* x    = (const float*)d_in[0];
    const int*   ei   = (const int*)  d_in[1];
    const int*   et   = (const int*)  d_in[2];
    const float* remb = (const float*)d_in[3];
    const float* rpw  = (const float*)d_in[4];
    const float* rpb  = (const float*)d_in[5];
    const float* Wr[3] = {(const float*)d_in[6],  (const float*)d_in[10], (const float*)d_in[14]};
    const float* Wo[3] = {(const float*)d_in[7],  (const float*)d_in[11], (const float*)d_in[15]};
    const float* Av[3] = {(const float*)d_in[8],  (const float*)d_in[12], (const float*)d_in[16]};
    const float* Ad[3] = {(const float*)d_in[9],  (const float*)d_in[13], (const float*)d_in[17]};

    int N = in_sizes[0] / HDIM;     // 20000
    int E = in_sizes[2];            // 400000
    const int* srcp = ei;
    const int* dstp = ei + E;

    float *root, *h1, *h2;
    __half *arth, *hrh;
    cudaGetSymbolAddress((void**)&hrh,  g_hrh);
    cudaGetSymbolAddress((void**)&root, g_root);
    cudaGetSymbolAddress((void**)&h1,   g_h1);
    cudaGetSymbolAddress((void**)&h2,   g_h2);
    cudaGetSymbolAddress((void**)&arth, g_arth);

    cudaFuncSetAttribute(k_mma, cudaFuncAttributeMaxDynamicSharedMemorySize, SMEM_BYTES);

    // ---- graph prep (layer-invariant) ----
    k_zero<<<(NMAX * RREL + 255) / 256, 256>>>();
    k_degcnt<<<(E + 255) / 256, 256>>>(dstp, et, E);
    k_scan<<<1, 1024>>>(N);
    k_fill<<<(E + 255) / 256, 256>>>(dstp, E);
    k_projrel<<<RREL, HDIM>>>(remb, rpw, rpb);
    k_relagg<<<N, HDIM>>>();
    int n4 = N * HDIM / 4;
    k_tohalf<<<(n4 + 255) / 256, 256>>>(x, arth, n4);

    // ---- three RGAT layers ----
    const float* hin = x;
    for (int l = 0; l < 3; l++) {
        int dob = (l == 2) ? ODIM : HDIM;
        int pitch = 9 * dob;

        dim3 gt(dob / 32, KDIM / 32, 9);
        k_repackT<<<gt, dim3(32, 8)>>>(Wr[l], Wo[l], dob);
        k_zsc<<<(N * 9 + 255) / 256, 256>>>(N * 9);

        dim3 g(pitch / BN, (N + BM - 1) / BM);
        k_mma<<<g, 256, SMEM_BYTES>>>(arth, hrh, root, N, dob, Av[l], Ad[l]);

        k_score<<<(E + 255) / 256, 256>>>(srcp, dstp, et, E, dob);

        float* hout = (l == 0) ? h1 : (l == 1) ? h2 : (float*)d_out;
        int wblocks = (N * 32 + 255) / 256;
        if (l == 2)
            k_agg<1><<<wblocks, 256>>>(hrh, root, hin, hout, arth, N);
        else
            k_agg<2><<<wblocks, 256>>>(hrh, root, hin, hout, arth, N);
        hin = hout;
    }
}